// round 10
// baseline (speedup 1.0000x reference)
#include <cuda_runtime.h>
#include <cstdint>
#include <math.h>

#define NPIX 4096
#define CC   256
#define CQ   64
#define BB   8
#define ROWS_ALL 384
#define LB   80            // tile row stride (bytes): 64 data + 16 pad
#define NC   64            // n-chunk
#define ITERS (NPIX/NC)

// ================= scratch (device globals) =================
__device__ float  g_Qf[(size_t)BB*NPIX*CQ];   // [b][n][cq] fp32
__device__ float  g_Kf[(size_t)BB*NPIX*CQ];   // [b][m][cq]
__device__ float  g_Vf[(size_t)BB*CC*NPIX];   // [b][c][n]  (gamma folded)
__device__ int8_t g_Qh[(size_t)BB*NPIX*CQ], g_Ql[(size_t)BB*NPIX*CQ];
__device__ int8_t g_Kh[(size_t)BB*NPIX*CQ], g_Kl[(size_t)BB*NPIX*CQ];
__device__ int8_t g_Vh[(size_t)BB*CC*NPIX], g_Vl[(size_t)BB*CC*NPIX];
__device__ float  g_Wall[ROWS_ALL*CC];
__device__ float  g_ball[ROWS_ALL];
__device__ unsigned g_amax[3];   // absmax bits: q, k, vg  (float bits, >=0)
__device__ unsigned g_n2[2];     // max row-norm^2 bits: q, k
__device__ float  g_scl[6];      // invSQ, invSK, invSV, sQK, invSS, sVS

// ================= PTX helpers =================
__device__ __forceinline__ uint32_t smem_u32(const void* p) {
    uint32_t a;
    asm("{ .reg .u64 t; cvta.to.shared.u64 t, %1; cvt.u32.u64 %0, t; }" : "=r"(a) : "l"(p));
    return a;
}
__device__ __forceinline__ void cpa16(uint32_t dst, const void* src) {
    asm volatile("cp.async.cg.shared.global [%0], [%1], 16;" :: "r"(dst), "l"(src));
}
#define CP_COMMIT() asm volatile("cp.async.commit_group;" ::: "memory")
#define CP_WAIT0()  asm volatile("cp.async.wait_group 0;" ::: "memory")

__device__ __forceinline__ void ldsm4(uint32_t r[4], uint32_t addr) {
    asm volatile("ldmatrix.sync.aligned.m8n8.x4.shared.b16 {%0,%1,%2,%3}, [%4];"
        : "=r"(r[0]), "=r"(r[1]), "=r"(r[2]), "=r"(r[3]) : "r"(addr));
}
__device__ __forceinline__ void imma(int c[4], const uint32_t a[4],
                                     uint32_t b0, uint32_t b1) {
    asm volatile(
        "mma.sync.aligned.m16n8k32.row.col.s32.s8.s8.s32 "
        "{%0,%1,%2,%3}, {%4,%5,%6,%7}, {%8,%9}, {%0,%1,%2,%3};"
        : "+r"(c[0]), "+r"(c[1]), "+r"(c[2]), "+r"(c[3])
        : "r"(a[0]), "r"(a[1]), "r"(a[2]), "r"(a[3]), "r"(b0), "r"(b1));
}
// elu without /N (deferred), exp via FFMA polynomial
__device__ __forceinline__ float elu_raw(float v) {
    float kf = rintf(v * 1.44269504f);
    float r  = fmaf(kf, -0.693145752f, v);
    r        = fmaf(kf, -1.42860677e-6f, r);
    float p  = 1.38888894e-3f;
    p = fmaf(p, r, 8.33333377e-3f);
    p = fmaf(p, r, 4.16666679e-2f);
    p = fmaf(p, r, 0.166666672f);
    p = fmaf(p, r, 0.5f);
    p = fmaf(p, r, 1.0f);
    p = fmaf(p, r, 1.0f);
    float sc = __uint_as_float((uint32_t)((127 + (int)kf) << 23));
    float e  = fmaf(p, sc, -1.0f);
    return v > 0.f ? v : e;
}
// 2-limb quantize: x ~ s*(h + l/252)
__device__ __forceinline__ void q2limb(float v, float inv, int &h, int &l) {
    float t = v * inv;
    h = __float2int_rn(t);
    h = max(-127, min(127, h));
    l = __float2int_rn((t - (float)h) * 252.f);
    l = max(-127, min(127, l));
}
__device__ __forceinline__ uint32_t pack4(int a, int b, int c, int d) {
    return (uint32_t)(a & 255) | ((uint32_t)(b & 255) << 8) |
           ((uint32_t)(c & 255) << 16) | ((uint32_t)(d & 255) << 24);
}

// ================= Kernel 0: weights (gamma folded into V) =================
__global__ void build_weights(const float* __restrict__ qw, const float* __restrict__ qb,
                              const float* __restrict__ kw, const float* __restrict__ kb,
                              const float* __restrict__ vw, const float* __restrict__ vb,
                              const float* __restrict__ gw) {
    int r = blockIdx.x, d = threadIdx.x;
    if (r < CQ) {
        g_Wall[r*CC + d] = qw[r*CC + d];
        if (d == 0) g_ball[r] = qb[r];
    } else if (r < 2*CQ) {
        g_Wall[r*CC + d] = kw[(r-CQ)*CC + d];
        if (d == 0) g_ball[r] = kb[r-CQ];
    } else {
        int c = r - 2*CQ;
        float acc = 0.f;
        for (int cp = 0; cp < CC; ++cp) acc = fmaf(gw[c*CC + cp], vw[cp*CC + d], acc);
        g_Wall[r*CC + d] = acc;
        if (d == 0) {
            float bacc = 0.f;
            for (int cp = 0; cp < CC; ++cp) bacc = fmaf(gw[c*CC + cp], vb[cp], bacc);
            g_ball[r] = bacc;
        }
    }
}

// ================= Kernel 1: projection (fp32) + absmax/norm stats =========
__global__ void __launch_bounds__(256) proj_kernel(const float* __restrict__ x) {
    __shared__ float Ws[16][64];
    __shared__ float Xs[16][64];
    __shared__ float red[256];
    __shared__ float nrm[64];
    int b = blockIdx.z, by = blockIdx.y, co0 = by * 64, n0 = blockIdx.x * 64;
    int t = threadIdx.x, tn = t % 16, tco = t / 16;
    const float* xb = x + (size_t)b * CC * NPIX;

    float acc[4][4];
    #pragma unroll
    for (int i = 0; i < 4; i++)
        #pragma unroll
        for (int j = 0; j < 4; j++) acc[i][j] = 0.f;

    for (int k0 = 0; k0 < CC; k0 += 16) {
        {
            int k = t % 16, co = t / 16;
            #pragma unroll
            for (int i = 0; i < 4; i++)
                Ws[k][co + 16*i] = g_Wall[(co0 + co + 16*i)*CC + k0 + k];
        }
        {
            int idx = t * 4, k = idx / 64, n = idx % 64;
            *(float4*)&Xs[k][n] = *(const float4*)&xb[(size_t)(k0 + k)*NPIX + n0 + n];
        }
        __syncthreads();
        #pragma unroll
        for (int k = 0; k < 16; k++) {
            float a[4], bx[4];
            #pragma unroll
            for (int i = 0; i < 4; i++) a[i] = Ws[k][tco + 16*i];
            #pragma unroll
            for (int j = 0; j < 4; j++) bx[j] = Xs[k][tn + 16*j];
            #pragma unroll
            for (int i = 0; i < 4; i++)
                #pragma unroll
                for (int j = 0; j < 4; j++) acc[i][j] = fmaf(a[i], bx[j], acc[i][j]);
        }
        __syncthreads();
    }

    // values (with bias) + writes
    float sv[4][4];
    #pragma unroll
    for (int i = 0; i < 4; i++) {
        int co = co0 + tco + 16*i;
        float bias = g_ball[co];
        #pragma unroll
        for (int j = 0; j < 4; j++) {
            int n = n0 + tn + 16*j;
            float s = acc[i][j] + bias;
            sv[i][j] = s;
            if (co < CQ)
                g_Qf[((size_t)b*NPIX + n)*CQ + co] = s;
            else if (co < 2*CQ)
                g_Kf[((size_t)b*NPIX + n)*CQ + (co - CQ)] = s;
            else
                g_Vf[((size_t)b*CC + (co - 2*CQ))*NPIX + n] = s;
        }
    }

    // ---- absmax block-reduce ----
    float lmax = 0.f;
    #pragma unroll
    for (int i = 0; i < 4; i++)
        #pragma unroll
        for (int j = 0; j < 4; j++) lmax = fmaxf(lmax, fabsf(sv[i][j]));
    red[t] = lmax;
    __syncthreads();
    for (int o = 128; o > 0; o >>= 1) {
        if (t < o) red[t] = fmaxf(red[t], red[t + o]);
        __syncthreads();
    }
    if (t == 0) {
        int region = (by == 0) ? 0 : (by == 1 ? 1 : 2);
        atomicMax(&g_amax[region], __float_as_uint(red[0]));
    }

    // ---- row-norm^2 (Q and K blocks only) ----
    if (t < 64) nrm[t] = 0.f;
    __syncthreads();
    if (by < 2) {
        #pragma unroll
        for (int j = 0; j < 4; j++) {
            float ss = sv[0][j]*sv[0][j] + sv[1][j]*sv[1][j]
                     + sv[2][j]*sv[2][j] + sv[3][j]*sv[3][j];
            atomicAdd(&nrm[tn + 16*j], ss);
        }
    }
    __syncthreads();
    if (by < 2 && t < 32) {
        float m = fmaxf(nrm[t], nrm[t + 32]);
        #pragma unroll
        for (int o = 16; o > 0; o >>= 1)
            m = fmaxf(m, __shfl_xor_sync(0xFFFFFFFFu, m, o));
        if (t == 0) atomicMax(&g_n2[by], __float_as_uint(m));
    }
}

// ================= Kernel 1b: finalize scales =================
__global__ void finalize_scales() {
    float qm = __uint_as_float(g_amax[0]);
    float km = __uint_as_float(g_amax[1]);
    float vm = __uint_as_float(g_amax[2]);
    float nq = sqrtf(__uint_as_float(g_n2[0]));
    float nk = sqrtf(__uint_as_float(g_n2[1]));
    float sQ = qm * (1.f/126.f), sK = km * (1.f/126.f), sV = vm * (1.f/126.f);
    float sS = nq * nk * (1.f/126.f);          // |S| <= ||q||*||k||
    g_scl[0] = 1.f / sQ;
    g_scl[1] = 1.f / sK;
    g_scl[2] = 1.f / sV;
    g_scl[3] = sQ * sK;
    g_scl[4] = 1.f / sS;
    g_scl[5] = sV * sS * (1.f/4096.f);
}

// ================= Kernel 1c: quantize fp32 -> 2x int8 limbs ================
#define NQE ((size_t)BB*NPIX*CQ)
#define NVE ((size_t)BB*CC*NPIX)
__global__ void __launch_bounds__(256) quantize_kernel() {
    const size_t nquad = (2*NQE + NVE) / 4;
    const float invq = g_scl[0], invk = g_scl[1], invv = g_scl[2];
    for (size_t q = (size_t)blockIdx.x*blockDim.x + threadIdx.x; q < nquad;
         q += (size_t)gridDim.x*blockDim.x) {
        size_t e = q * 4, off;
        const float* src; int8_t *dh, *dl; float inv;
        if (e < NQE)        { off = e;         src = g_Qf + off; dh = g_Qh; dl = g_Ql; inv = invq; }
        else if (e < 2*NQE) { off = e - NQE;   src = g_Kf + off; dh = g_Kh; dl = g_Kl; inv = invk; }
        else                { off = e - 2*NQE; src = g_Vf + off; dh = g_Vh; dl = g_Vl; inv = invv; }
        float4 v = *(const float4*)src;
        int h0,l0,h1,l1,h2,l2,h3,l3;
        q2limb(v.x, inv, h0, l0);
        q2limb(v.y, inv, h1, l1);
        q2limb(v.z, inv, h2, l2);
        q2limb(v.w, inv, h3, l3);
        *(uint32_t*)(dh + off) = pack4(h0, h1, h2, h3);
        *(uint32_t*)(dl + off) = pack4(l0, l1, l2, l3);
    }
}

// ================= Kernel 2: fused attention via IMMA =======================
// smem (bytes), row stride LB=80
#define KH_O 0
#define KL_O 5120
#define SH_O 10240
#define SL_O 15360
#define QH_ST(s) (20480 + (s)*10240)
#define QL_ST(s) (QH_ST(s) + 5120)
#define VH_ST(s) (40960 + (s)*40960)
#define VL_ST(s) (VH_ST(s) + 20480)
#define SMEM_BYTES 122880

__global__ void __launch_bounds__(256) attn_imma(float* __restrict__ out,
                                                 const float* __restrict__ gbias) {
    extern __shared__ char sm[];
    const uint32_t sb = smem_u32(sm);
    const int tid = threadIdx.x, wid = tid >> 5, lane = tid & 31;
    const int g = lane >> 2, t4 = lane & 3;
    const int b = blockIdx.y, m0 = blockIdx.x * 64;
    const int lrow = lane & 15;
    const int lcol = (lane >> 4) * 16;          // 16-byte half of the 32-byte k-chunk

    const int w1m = (wid & 1) * 32, w1n = (wid >> 1) * 16;   // GEMM1 warp tile [32m x 16n]
    const int w2c = (wid >> 1) * 64, w2m = (wid & 1) * 32;   // GEMM2 warp tile [64c x 32m]

    const float sQK   = g_scl[3];
    const float invSS = g_scl[4];
    const float sVS   = g_scl[5];
    const float inv252 = 1.f / 252.f;

    auto issue_stage = [&](int s, int n0) {
        int row = tid >> 2, ch = (tid & 3) * 16;
        cpa16(sb + QH_ST(s) + row*LB + ch, g_Qh + ((size_t)b*NPIX + n0 + row)*CQ + ch);
        cpa16(sb + QL_ST(s) + row*LB + ch, g_Ql + ((size_t)b*NPIX + n0 + row)*CQ + ch);
        #pragma unroll
        for (int r = 0; r < 4; r++) {
            int id = tid + 256*r, vrow = id >> 2, vch = (id & 3) * 16;
            cpa16(sb + VH_ST(s) + vrow*LB + vch, g_Vh + ((size_t)b*CC + vrow)*NPIX + n0 + vch);
            cpa16(sb + VL_ST(s) + vrow*LB + vch, g_Vl + ((size_t)b*CC + vrow)*NPIX + n0 + vch);
        }
    };

    {   // K prologue + first Q/V stage
        int row = tid >> 2, ch = (tid & 3) * 16;
        cpa16(sb + KH_O + row*LB + ch, g_Kh + ((size_t)b*NPIX + m0 + row)*CQ + ch);
        cpa16(sb + KL_O + row*LB + ch, g_Kl + ((size_t)b*NPIX + m0 + row)*CQ + ch);
        issue_stage(0, 0);
        CP_COMMIT();
    }

    int ohh[4][4][4], ox[4][4][4];
    #pragma unroll
    for (int i = 0; i < 4; i++)
        #pragma unroll
        for (int j = 0; j < 4; j++)
            #pragma unroll
            for (int q = 0; q < 4; q++) { ohh[i][j][q] = 0; ox[i][j][q] = 0; }

    for (int it = 0; it < ITERS; ++it) {
        const int buf = it & 1;
        CP_WAIT0();
        __syncthreads();
        if (it < ITERS-1) { issue_stage(buf ^ 1, (it + 1) * NC); CP_COMMIT(); }

        const uint32_t QH = QH_ST(buf), QL = QL_ST(buf);
        const uint32_t VH = VH_ST(buf), VL = VL_ST(buf);

        // ---- GEMM1: S[32m x 16n] = K·Q (3-product 2-limb) ----
        int shh[2][2][4], sx[2][2][4];
        #pragma unroll
        for (int i = 0; i < 2; i++)
            #pragma unroll
            for (int j = 0; j < 2; j++)
                #pragma unroll
                for (int q = 0; q < 4; q++) { shh[i][j][q] = 0; sx[i][j][q] = 0; }

        #pragma unroll
        for (int kk = 0; kk < 2; kk++) {
            const int C = kk * 32 + lcol;
            uint32_t ah0[4], ah1[4], al0[4], al1[4], qh[4], ql[4];
            ldsm4(ah0, sb + KH_O + (w1m      + lrow)*LB + C);
            ldsm4(ah1, sb + KH_O + (w1m + 16 + lrow)*LB + C);
            ldsm4(al0, sb + KL_O + (w1m      + lrow)*LB + C);
            ldsm4(al1, sb + KL_O + (w1m + 16 + lrow)*LB + C);
            ldsm4(qh,  sb + QH   + (w1n + lrow)*LB + C);
            ldsm4(ql,  sb + QL   + (w1n + lrow)*LB + C);
            imma(shh[0][0], ah0, qh[0], qh[2]);
            imma(shh[0][1], ah0, qh[1], qh[3]);
            imma(shh[1][0], ah1, qh[0], qh[2]);
            imma(shh[1][1], ah1, qh[1], qh[3]);
            imma(sx[0][0], ah0, ql[0], ql[2]);
            imma(sx[0][1], ah0, ql[1], ql[3]);
            imma(sx[1][0], ah1, ql[0], ql[2]);
            imma(sx[1][1], ah1, ql[1], ql[3]);
            imma(sx[0][0], al0, qh[0], qh[2]);
            imma(sx[0][1], al0, qh[1], qh[3]);
            imma(sx[1][0], al1, qh[0], qh[2]);
            imma(sx[1][1], al1, qh[1], qh[3]);
        }

        // ---- elu + quantize + store S limbs, layout [m][n bytes] ----
        #pragma unroll
        for (int i = 0; i < 2; i++)
            #pragma unroll
            for (int j = 0; j < 2; j++) {
                int rb = w1m + 16*i + g;
                int cb = w1n + 8*j + t4*2;
                #pragma unroll
                for (int hrow = 0; hrow < 2; hrow++) {
                    float f0 = sQK * ((float)shh[i][j][2*hrow]   + inv252 * (float)sx[i][j][2*hrow]);
                    float f1 = sQK * ((float)shh[i][j][2*hrow+1] + inv252 * (float)sx[i][j][2*hrow+1]);
                    float e0 = elu_raw(f0), e1 = elu_raw(f1);
                    int h0, l0, h1, l1;
                    q2limb(e0, invSS, h0, l0);
                    q2limb(e1, invSS, h1, l1);
                    int r2 = rb + 8*hrow;
                    *(uint16_t*)(sm + SH_O + r2*LB + cb) =
                        (uint16_t)((h0 & 255) | ((h1 & 255) << 8));
                    *(uint16_t*)(sm + SL_O + r2*LB + cb) =
                        (uint16_t)((l0 & 255) | ((l1 & 255) << 8));
                }
            }
        __syncthreads();

        // ---- GEMM2: O[64c x 32m] += VG·S (3-product 2-limb, exact int acc) ----
        #pragma unroll
        for (int kk = 0; kk < 2; kk++) {
            const int C = kk * 32 + lcol;
            uint32_t vh[4][4], vl[4][4], sh0[4], sh1[4], sl0[4], sl1[4];
            #pragma unroll
            for (int i = 0; i < 4; i++) {
                ldsm4(vh[i], sb + VH + (w2c + 16*i + lrow)*LB + C);
                ldsm4(vl[i], sb + VL + (w2c + 16*i + lrow)*LB + C);
            }
            ldsm4(sh0, sb + SH_O + (w2m      + lrow)*LB + C);
            ldsm4(sh1, sb + SH_O + (w2m + 16 + lrow)*LB + C);
            ldsm4(sl0, sb + SL_O + (w2m      + lrow)*LB + C);
            ldsm4(sl1, sb + SL_O + (w2m + 16 + lrow)*LB + C);
            #pragma unroll
            for (int i = 0; i < 4; i++) {
                imma(ohh[i][0], vh[i], sh0[0], sh0[2]);
                imma(ohh[i][1], vh[i], sh0[1], sh0[3]);
                imma(ohh[i][2], vh[i], sh1[0], sh1[2]);
                imma(ohh[i][3], vh[i], sh1[1], sh1[3]);
                imma(ox[i][0], vh[i], sl0[0], sl0[2]);
                imma(ox[i][1], vh[i], sl0[1], sl0[3]);
                imma(ox[i][2], vh[i], sl1[0], sl1[2]);
                imma(ox[i][3], vh[i], sl1[1], sl1[3]);
                imma(ox[i][0], vl[i], sh0[0], sh0[2]);
                imma(ox[i][1], vl[i], sh0[1], sh0[3]);
                imma(ox[i][2], vl[i], sh1[0], sh1[2]);
                imma(ox[i][3], vl[i], sh1[1], sh1[3]);
            }
        }
    }

    // ---- epilogue: out = sV*sS*(HH + X/252)/4096 + gbias[c] ----
    #pragma unroll
    for (int i = 0; i < 4; i++) {
        int c  = w2c + 16*i + g;
        float b0 = gbias[c], b8 = gbias[c + 8];
        #pragma unroll
        for (int j = 0; j < 4; j++) {
            int m = m0 + w2m + 8*j + t4*2;
            float2 v0;
            v0.x = fmaf(sVS, (float)ohh[i][j][0] + inv252*(float)ox[i][j][0], b0);
            v0.y = fmaf(sVS, (float)ohh[i][j][1] + inv252*(float)ox[i][j][1], b0);
            *(float2*)&out[((size_t)b*CC + c)*NPIX + m] = v0;
            float2 v1;
            v1.x = fmaf(sVS, (float)ohh[i][j][2] + inv252*(float)ox[i][j][2], b8);
            v1.y = fmaf(sVS, (float)ohh[i][j][3] + inv252*(float)ox[i][j][3], b8);
            *(float2*)&out[((size_t)b*CC + c + 8)*NPIX + m] = v1;
        }
    }
}

// ================= launch =================
extern "C" void kernel_launch(void* const* d_in, const int* in_sizes, int n_in,
                              void* d_out, int out_size) {
    const float* x  = (const float*)d_in[0];
    const float* qw = (const float*)d_in[1];
    const float* qb = (const float*)d_in[2];
    const float* kw = (const float*)d_in[3];
    const float* kb = (const float*)d_in[4];
    const float* vw = (const float*)d_in[5];
    const float* vb = (const float*)d_in[6];
    const float* gw = (const float*)d_in[7];
    const float* gb = (const float*)d_in[8];
    float* out = (float*)d_out;

    cudaFuncSetAttribute(attn_imma, cudaFuncAttributeMaxDynamicSharedMemorySize, SMEM_BYTES);

    build_weights<<<ROWS_ALL, 256>>>(qw, qb, kw, kb, vw, vb, gw);
    proj_kernel<<<dim3(64, 6, BB), 256>>>(x);
    finalize_scales<<<1, 1>>>();
    quantize_kernel<<<4096, 256>>>();
    attn_imma<<<dim3(64, BB), 256, SMEM_BYTES>>>(out, gb);
}

// round 11
// speedup vs baseline: 3.6911x; 3.6911x over previous
#include <cuda_runtime.h>
#include <cuda_fp16.h>
#include <cstdint>

#define NPIX 4096
#define CC   256
#define CQ   64
#define BB   8
#define ROWS_ALL 384
#define LD   72   // smem row stride in halves

// ================= scratch (device globals) =================
__device__ __half g_Q[(size_t)BB*NPIX*CQ];   // [b][n][cq]
__device__ __half g_K[(size_t)BB*NPIX*CQ];   // [b][m][cq]
__device__ __half g_V[(size_t)BB*CC*NPIX];   // [b][c][n]  (gamma folded)
__device__ float g_Wall[ROWS_ALL*CC];
__device__ float g_ball[ROWS_ALL];

// ================= PTX helpers =================
__device__ __forceinline__ uint32_t smem_u32(const void* p) {
    uint32_t a;
    asm("{ .reg .u64 t; cvta.to.shared.u64 t, %1; cvt.u32.u64 %0, t; }" : "=r"(a) : "l"(p));
    return a;
}
__device__ __forceinline__ void cpa16(uint32_t dst, const void* src) {
    asm volatile("cp.async.cg.shared.global [%0], [%1], 16;" :: "r"(dst), "l"(src));
}
#define CP_COMMIT() asm volatile("cp.async.commit_group;" ::: "memory")
#define CP_WAIT0()  asm volatile("cp.async.wait_group 0;" ::: "memory")

__device__ __forceinline__ void ldsm4(uint32_t r[4], uint32_t addr) {
    asm volatile("ldmatrix.sync.aligned.m8n8.x4.shared.b16 {%0,%1,%2,%3}, [%4];"
        : "=r"(r[0]), "=r"(r[1]), "=r"(r[2]), "=r"(r[3]) : "r"(addr));
}
__device__ __forceinline__ void mmah(float c[4], const uint32_t a[4],
                                     uint32_t b0, uint32_t b1) {
    asm volatile(
        "mma.sync.aligned.m16n8k16.row.col.f32.f16.f16.f32 "
        "{%0,%1,%2,%3}, {%4,%5,%6,%7}, {%8,%9}, {%0,%1,%2,%3};"
        : "+f"(c[0]), "+f"(c[1]), "+f"(c[2]), "+f"(c[3])
        : "r"(a[0]), "r"(a[1]), "r"(a[2]), "r"(a[3]), "r"(b0), "r"(b1));
}
// pack two f32 -> f16x2 (e0 low, e1 high)
__device__ __forceinline__ uint32_t packh(float e0, float e1) {
    uint32_t r; asm("cvt.rn.f16x2.f32 %0, %1, %2;" : "=r"(r) : "f"(e1), "f"(e0)); return r;
}
// elu without /N (deferred), exp via FFMA polynomial
__device__ __forceinline__ float elu_raw(float v) {
    float kf = rintf(v * 1.44269504f);
    float r  = fmaf(kf, -0.693145752f, v);
    r        = fmaf(kf, -1.42860677e-6f, r);
    float p  = 1.38888894e-3f;
    p = fmaf(p, r, 8.33333377e-3f);
    p = fmaf(p, r, 4.16666679e-2f);
    p = fmaf(p, r, 0.166666672f);
    p = fmaf(p, r, 0.5f);
    p = fmaf(p, r, 1.0f);
    p = fmaf(p, r, 1.0f);
    float sc = __uint_as_float((uint32_t)((127 + (int)kf) << 23));
    float e  = fmaf(p, sc, -1.0f);
    return v > 0.f ? v : e;
}

// ================= Kernel 0: weights (gamma folded into V) =================
__global__ void build_weights(const float* __restrict__ qw, const float* __restrict__ qb,
                              const float* __restrict__ kw, const float* __restrict__ kb,
                              const float* __restrict__ vw, const float* __restrict__ vb,
                              const float* __restrict__ gw) {
    int r = blockIdx.x, d = threadIdx.x;
    if (r < CQ) {
        g_Wall[r*CC + d] = qw[r*CC + d];
        if (d == 0) g_ball[r] = qb[r];
    } else if (r < 2*CQ) {
        g_Wall[r*CC + d] = kw[(r-CQ)*CC + d];
        if (d == 0) g_ball[r] = kb[r-CQ];
    } else {
        int c = r - 2*CQ;
        float acc = 0.f;
        for (int cp = 0; cp < CC; ++cp) acc = fmaf(gw[c*CC + cp], vw[cp*CC + d], acc);
        g_Wall[r*CC + d] = acc;
        if (d == 0) {
            float bacc = 0.f;
            for (int cp = 0; cp < CC; ++cp) bacc = fmaf(gw[c*CC + cp], vb[cp], bacc);
            g_ball[r] = bacc;
        }
    }
}

// ================= Kernel 1: projection (fp32), writes fp16 ================
__global__ void __launch_bounds__(256) proj_kernel(const float* __restrict__ x) {
    __shared__ float Ws[16][64];
    __shared__ float Xs[16][64];
    int b = blockIdx.z, co0 = blockIdx.y * 64, n0 = blockIdx.x * 64;
    int t = threadIdx.x, tn = t % 16, tco = t / 16;
    const float* xb = x + (size_t)b * CC * NPIX;

    float acc[4][4];
    #pragma unroll
    for (int i = 0; i < 4; i++)
        #pragma unroll
        for (int j = 0; j < 4; j++) acc[i][j] = 0.f;

    for (int k0 = 0; k0 < CC; k0 += 16) {
        {
            int k = t % 16, co = t / 16;
            #pragma unroll
            for (int i = 0; i < 4; i++)
                Ws[k][co + 16*i] = g_Wall[(co0 + co + 16*i)*CC + k0 + k];
        }
        {
            int idx = t * 4, k = idx / 64, n = idx % 64;
            *(float4*)&Xs[k][n] = *(const float4*)&xb[(size_t)(k0 + k)*NPIX + n0 + n];
        }
        __syncthreads();
        #pragma unroll
        for (int k = 0; k < 16; k++) {
            float a[4], bx[4];
            #pragma unroll
            for (int i = 0; i < 4; i++) a[i] = Ws[k][tco + 16*i];
            #pragma unroll
            for (int j = 0; j < 4; j++) bx[j] = Xs[k][tn + 16*j];
            #pragma unroll
            for (int i = 0; i < 4; i++)
                #pragma unroll
                for (int j = 0; j < 4; j++) acc[i][j] = fmaf(a[i], bx[j], acc[i][j]);
        }
        __syncthreads();
    }

    #pragma unroll
    for (int i = 0; i < 4; i++) {
        int co = co0 + tco + 16*i;
        float bias = g_ball[co];
        #pragma unroll
        for (int j = 0; j < 4; j++) {
            int n = n0 + tn + 16*j;
            __half h = __float2half(acc[i][j] + bias);
            if (co < CQ)
                g_Q[((size_t)b*NPIX + n)*CQ + co] = h;
            else if (co < 2*CQ)
                g_K[((size_t)b*NPIX + n)*CQ + (co - CQ)] = h;
            else
                g_V[((size_t)b*CC + (co - 2*CQ))*NPIX + n] = h;
        }
    }
}

// ================= Kernel 2: fused attention, fp16 single-product ==========
// smem (halves): K | S | Q x2 | V x2
#define SM_K  0
#define SM_S  4608
#define Q_ST(s) (9216 + (s)*4608)
#define V_ST(s) (18432 + (s)*18432)
#define SMEM_HALVES (18432 + 2*18432)
#define SMEM_BYTES  (SMEM_HALVES*2)

__global__ void __launch_bounds__(256) attn_mma(float* __restrict__ out,
                                                const float* __restrict__ gbias) {
    extern __shared__ __half sm[];
    const uint32_t sb = smem_u32(sm);
    const int tid = threadIdx.x, wid = tid >> 5, lane = tid & 31;
    const int g = lane >> 2, t4 = lane & 3;
    const int b = blockIdx.y, m0 = blockIdx.x * 64;
    const int lrow = lane & 15, lcol = (lane >> 4) * 8;

    const int w1m = (wid & 1) * 32, w1n = (wid >> 1) * 16;   // GEMM1 [32m x 16n]
    const int w2c = (wid >> 1) * 64, w2m = (wid & 1) * 32;   // GEMM2 [64c x 32m]

    #define SMB(idx) (sb + (uint32_t)(idx) * 2u)

    auto issue_stage = [&](int s, int n0) {
        const __half* q = g_Q + ((size_t)b*NPIX + n0)*CQ;
        #pragma unroll
        for (int r = 0; r < 2; r++) {
            int id = tid + 256*r, row = id >> 3, ch = (id & 7) * 8;
            cpa16(SMB(Q_ST(s) + row*LD + ch), q + (size_t)row*CQ + ch);
        }
        const __half* v = g_V + (size_t)b*CC*NPIX + n0;
        #pragma unroll
        for (int r = 0; r < 8; r++) {
            int id = tid + 256*r, row = id >> 3, ch = (id & 7) * 8;
            cpa16(SMB(V_ST(s) + row*LD + ch), v + (size_t)row*NPIX + ch);
        }
    };

    {   // K prologue (group 0, with stage 0)
        const __half* k = g_K + ((size_t)b*NPIX + m0)*CQ;
        #pragma unroll
        for (int r = 0; r < 2; r++) {
            int id = tid + 256*r, row = id >> 3, ch = (id & 7) * 8;
            cpa16(SMB(SM_K + row*LD + ch), k + (size_t)row*CQ + ch);
        }
    }
    issue_stage(0, 0);
    CP_COMMIT();

    float acc[4][4][4];
    #pragma unroll
    for (int i = 0; i < 4; i++)
        #pragma unroll
        for (int j = 0; j < 4; j++)
            #pragma unroll
            for (int q = 0; q < 4; q++) acc[i][j][q] = 0.f;

    for (int it = 0; it < 64; ++it) {
        const int buf = it & 1;
        CP_WAIT0();
        __syncthreads();   // data landed (all threads) + prev GEMM2 done with S
        if (it < 63) { issue_stage(buf ^ 1, (it + 1) * 64); CP_COMMIT(); }

        const uint32_t QO = Q_ST(buf), VO = V_ST(buf);

        // ---- GEMM1: S[m][n] = K·Q ----
        float sacc[2][2][4];
        #pragma unroll
        for (int i = 0; i < 2; i++)
            #pragma unroll
            for (int j = 0; j < 2; j++)
                #pragma unroll
                for (int q = 0; q < 4; q++) sacc[i][j][q] = 0.f;

        #pragma unroll
        for (int kk = 0; kk < 4; kk++) {
            const int C = kk * 16 + lcol;
            uint32_t k0[4], k1[4], qv[4];
            ldsm4(k0, SMB(SM_K + (w1m      + lrow)*LD + C));
            ldsm4(k1, SMB(SM_K + (w1m + 16 + lrow)*LD + C));
            ldsm4(qv, SMB(QO   + (w1n      + lrow)*LD + C));
            mmah(sacc[0][0], k0, qv[0], qv[2]);
            mmah(sacc[0][1], k0, qv[1], qv[3]);
            mmah(sacc[1][0], k1, qv[0], qv[2]);
            mmah(sacc[1][1], k1, qv[1], qv[3]);
        }

        // ---- elu + store S (fp16), layout [m][n] ----
        #pragma unroll
        for (int i = 0; i < 2; i++)
            #pragma unroll
            for (int j = 0; j < 2; j++) {
                int row = w1m + 16*i + g;
                int col = w1n + 8*j + t4*2;
                *(uint32_t*)&sm[SM_S + row*LD + col] =
                    packh(elu_raw(sacc[i][j][0]), elu_raw(sacc[i][j][1]));
                *(uint32_t*)&sm[SM_S + (row+8)*LD + col] =
                    packh(elu_raw(sacc[i][j][2]), elu_raw(sacc[i][j][3]));
            }
        __syncthreads();

        // ---- GEMM2: O[c][m] += V·S ----
        #pragma unroll
        for (int kk = 0; kk < 4; kk++) {
            const int C = kk * 16 + lcol;
            uint32_t vv[4][4], s0[4], s1[4];
            #pragma unroll
            for (int i = 0; i < 4; i++)
                ldsm4(vv[i], SMB(VO + (w2c + 16*i + lrow)*LD + C));
            ldsm4(s0, SMB(SM_S + (w2m      + lrow)*LD + C));
            ldsm4(s1, SMB(SM_S + (w2m + 16 + lrow)*LD + C));
            #pragma unroll
            for (int i = 0; i < 4; i++) {
                mmah(acc[i][0], vv[i], s0[0], s0[2]);
                mmah(acc[i][1], vv[i], s0[1], s0[3]);
                mmah(acc[i][2], vv[i], s1[0], s1[2]);
                mmah(acc[i][3], vv[i], s1[1], s1[3]);
            }
        }
    }

    // ---- epilogue: out = acc/4096 + gbias[c] ----
    const float inv = 1.0f / 4096.0f;
    #pragma unroll
    for (int i = 0; i < 4; i++) {
        int c  = w2c + 16*i + g;
        float b0 = gbias[c], b8 = gbias[c + 8];
        #pragma unroll
        for (int j = 0; j < 4; j++) {
            int m = m0 + w2m + 8*j + t4*2;
            float2 v0 = { fmaf(acc[i][j][0], inv, b0), fmaf(acc[i][j][1], inv, b0) };
            *(float2*)&out[((size_t)b*CC + c)*NPIX + m] = v0;
            float2 v1 = { fmaf(acc[i][j][2], inv, b8), fmaf(acc[i][j][3], inv, b8) };
            *(float2*)&out[((size_t)b*CC + c + 8)*NPIX + m] = v1;
        }
    }
}

// ================= launch =================
extern "C" void kernel_launch(void* const* d_in, const int* in_sizes, int n_in,
                              void* d_out, int out_size) {
    const float* x  = (const float*)d_in[0];
    const float* qw = (const float*)d_in[1];
    const float* qb = (const float*)d_in[2];
    const float* kw = (const float*)d_in[3];
    const float* kb = (const float*)d_in[4];
    const float* vw = (const float*)d_in[5];
    const float* vb = (const float*)d_in[6];
    const float* gw = (const float*)d_in[7];
    const float* gb = (const float*)d_in[8];
    float* out = (float*)d_out;

    cudaFuncSetAttribute(attn_mma, cudaFuncAttributeMaxDynamicSharedMemorySize, SMEM_BYTES);

    build_weights<<<ROWS_ALL, 256>>>(qw, qb, kw, kb, vw, vb, gw);
    proj_kernel<<<dim3(64, 6, BB), 256>>>(x);
    attn_mma<<<dim3(64, BB), 256, SMEM_BYTES>>>(out, gb);
}

// round 12
// speedup vs baseline: 5.9050x; 1.5998x over previous
#include <cuda_runtime.h>
#include <cuda_fp16.h>
#include <cstdint>

#define NPIX 4096
#define CC   256
#define CQ   64
#define BB   8
#define ROWS_ALL 384
#define LD   72    // attn smem row stride (halves)
#define LDW  264   // proj W tile stride (halves)
#define LDX  136   // proj x tile stride (halves)
#define LDT  136   // proj transpose-stage stride (halves)

// ================= scratch (device globals) =================
__device__ __half g_Q[(size_t)BB*NPIX*CQ];   // [b][n][cq]
__device__ __half g_K[(size_t)BB*NPIX*CQ];   // [b][m][cq]
__device__ __half g_V[(size_t)BB*CC*NPIX];   // [b][c][n]  (gamma folded)
__device__ __half g_xh[(size_t)BB*CC*NPIX];  // x in fp16, [b][k][n]
__device__ __half g_Wh[ROWS_ALL*CC];         // fused weights fp16 [row][k]
__device__ float  g_ball[ROWS_ALL];

// ================= PTX helpers =================
__device__ __forceinline__ uint32_t smem_u32(const void* p) {
    uint32_t a;
    asm("{ .reg .u64 t; cvta.to.shared.u64 t, %1; cvt.u32.u64 %0, t; }" : "=r"(a) : "l"(p));
    return a;
}
__device__ __forceinline__ void cpa16(uint32_t dst, const void* src) {
    asm volatile("cp.async.cg.shared.global [%0], [%1], 16;" :: "r"(dst), "l"(src));
}
#define CP_COMMIT() asm volatile("cp.async.commit_group;" ::: "memory")
#define CP_WAIT0()  asm volatile("cp.async.wait_group 0;" ::: "memory")

__device__ __forceinline__ void ldsm4(uint32_t r[4], uint32_t addr) {
    asm volatile("ldmatrix.sync.aligned.m8n8.x4.shared.b16 {%0,%1,%2,%3}, [%4];"
        : "=r"(r[0]), "=r"(r[1]), "=r"(r[2]), "=r"(r[3]) : "r"(addr));
}
__device__ __forceinline__ void ldsm4t(uint32_t r[4], uint32_t addr) {
    asm volatile("ldmatrix.sync.aligned.m8n8.x4.trans.shared.b16 {%0,%1,%2,%3}, [%4];"
        : "=r"(r[0]), "=r"(r[1]), "=r"(r[2]), "=r"(r[3]) : "r"(addr));
}
__device__ __forceinline__ void mmah(float c[4], const uint32_t a[4],
                                     uint32_t b0, uint32_t b1) {
    asm volatile(
        "mma.sync.aligned.m16n8k16.row.col.f32.f16.f16.f32 "
        "{%0,%1,%2,%3}, {%4,%5,%6,%7}, {%8,%9}, {%0,%1,%2,%3};"
        : "+f"(c[0]), "+f"(c[1]), "+f"(c[2]), "+f"(c[3])
        : "r"(a[0]), "r"(a[1]), "r"(a[2]), "r"(a[3]), "r"(b0), "r"(b1));
}
__device__ __forceinline__ uint32_t packh(float e0, float e1) {
    uint32_t r; asm("cvt.rn.f16x2.f32 %0, %1, %2;" : "=r"(r) : "f"(e1), "f"(e0)); return r;
}
// elu without /N (deferred), exp via FFMA polynomial
__device__ __forceinline__ float elu_raw(float v) {
    float kf = rintf(v * 1.44269504f);
    float r  = fmaf(kf, -0.693145752f, v);
    r        = fmaf(kf, -1.42860677e-6f, r);
    float p  = 1.38888894e-3f;
    p = fmaf(p, r, 8.33333377e-3f);
    p = fmaf(p, r, 4.16666679e-2f);
    p = fmaf(p, r, 0.166666672f);
    p = fmaf(p, r, 0.5f);
    p = fmaf(p, r, 1.0f);
    p = fmaf(p, r, 1.0f);
    float sc = __uint_as_float((uint32_t)((127 + (int)kf) << 23));
    float e  = fmaf(p, sc, -1.0f);
    return v > 0.f ? v : e;
}

// ================= Kernel 0: weights (gamma folded into V), fp16 out =======
__global__ void build_weights(const float* __restrict__ qw, const float* __restrict__ qb,
                              const float* __restrict__ kw, const float* __restrict__ kb,
                              const float* __restrict__ vw, const float* __restrict__ vb,
                              const float* __restrict__ gw) {
    int r = blockIdx.x, d = threadIdx.x;
    if (r < CQ) {
        g_Wh[r*CC + d] = __float2half(qw[r*CC + d]);
        if (d == 0) g_ball[r] = qb[r];
    } else if (r < 2*CQ) {
        g_Wh[r*CC + d] = __float2half(kw[(r-CQ)*CC + d]);
        if (d == 0) g_ball[r] = kb[r-CQ];
    } else {
        int c = r - 2*CQ;
        float acc = 0.f;
        for (int cp = 0; cp < CC; ++cp) acc = fmaf(gw[c*CC + cp], vw[cp*CC + d], acc);
        g_Wh[r*CC + d] = __float2half(acc);
        if (d == 0) {
            float bacc = 0.f;
            for (int cp = 0; cp < CC; ++cp) bacc = fmaf(gw[c*CC + cp], vb[cp], bacc);
            g_ball[r] = bacc;
        }
    }
}

// ================= Kernel 0b: x -> fp16 =================
__global__ void __launch_bounds__(256) cvt_x(const float* __restrict__ x) {
    size_t nq = (size_t)BB*CC*NPIX / 4;
    for (size_t q = (size_t)blockIdx.x*blockDim.x + threadIdx.x; q < nq;
         q += (size_t)gridDim.x*blockDim.x) {
        float4 v = *(const float4*)(x + q*4);
        uint2 o;
        o.x = packh(v.x, v.y);
        o.y = packh(v.z, v.w);
        *(uint2*)(g_xh + q*4) = o;
    }
}

// ================= Kernel 1: projection via HMMA ============================
// Block tile [128co x 128n], 8 warps = 4(co) x 2(n), warp tile [32co x 64n].
// K=256 in 8 chunks of 32, cp.async double-buffered.
// smem: W[128][LDW] @0 (67584 B), x stages 2x[32][LDX] (8704 B each)
#define PW_O 0
#define PX_ST(s) (33792 + (s)*4352)   // in halves: 67584/2=33792, 8704/2=4352
#define PROJ_SMEM 84992

__global__ void __launch_bounds__(256) proj_mma(const float* __restrict__ unused) {
    extern __shared__ __half psm[];
    const uint32_t sb = smem_u32(psm);
    const int tid = threadIdx.x, wid = tid >> 5, lane = tid & 31;
    const int g = lane >> 2, t4 = lane & 3;
    const int lrow = lane & 15, lcol = (lane >> 4) * 8;
    const int b = blockIdx.z, co0 = blockIdx.y * 128, n0 = blockIdx.x * 128;

    const int wc = (wid & 3) * 32;        // warp co offset
    const int wn = (wid >> 2) * 64;       // warp n offset

    #define PSB(idx) (sb + (uint32_t)(idx) * 2u)

    // prologue: W tile [128 rows][256 k] + x stage 0
    {
        const __half* wsrc = g_Wh + (size_t)co0 * CC;
        #pragma unroll
        for (int r = 0; r < 16; r++) {
            int id = tid + 256*r, row = id >> 5, ch = (id & 31) * 8;
            cpa16(PSB(PW_O + row*LDW + ch), wsrc + (size_t)row*CC + ch);
        }
        const __half* xsrc = g_xh + ((size_t)b*CC + 0)*NPIX + n0;
        #pragma unroll
        for (int r = 0; r < 2; r++) {
            int id = tid + 256*r, k = id >> 4, ch = (id & 15) * 8;
            cpa16(PSB(PX_ST(0) + k*LDX + ch), xsrc + (size_t)k*NPIX + ch);
        }
        CP_COMMIT();
    }

    float acc[2][8][4];
    #pragma unroll
    for (int i = 0; i < 2; i++)
        #pragma unroll
        for (int j = 0; j < 8; j++)
            #pragma unroll
            for (int q = 0; q < 4; q++) acc[i][j][q] = 0.f;

    for (int kc = 0; kc < 8; ++kc) {
        const int buf = kc & 1;
        CP_WAIT0();
        __syncthreads();
        if (kc < 7) {
            const __half* xsrc = g_xh + ((size_t)b*CC + (kc+1)*32)*NPIX + n0;
            #pragma unroll
            for (int r = 0; r < 2; r++) {
                int id = tid + 256*r, k = id >> 4, ch = (id & 15) * 8;
                cpa16(PSB(PX_ST(buf^1) + k*LDX + ch), xsrc + (size_t)k*NPIX + ch);
            }
            CP_COMMIT();
        }
        const uint32_t XO = PX_ST(buf);
        #pragma unroll
        for (int ks = 0; ks < 2; ++ks) {
            const int kk = kc*32 + ks*16;
            uint32_t a0[4], a1[4];
            ldsm4(a0, PSB(PW_O + (wc      + lrow)*LDW + kk + lcol));
            ldsm4(a1, PSB(PW_O + (wc + 16 + lrow)*LDW + kk + lcol));
            #pragma unroll
            for (int nt = 0; nt < 4; ++nt) {
                uint32_t bx[4];
                ldsm4t(bx, PSB(XO + (ks*16 + lrow)*LDX + wn + nt*16 + lcol));
                mmah(acc[0][2*nt],   a0, bx[0], bx[1]);
                mmah(acc[0][2*nt+1], a0, bx[2], bx[3]);
                mmah(acc[1][2*nt],   a1, bx[0], bx[1]);
                mmah(acc[1][2*nt+1], a1, bx[2], bx[3]);
            }
        }
        __syncthreads();   // protect x stage buf from next-next overwrite
    }

    if (co0 >= 128) {
        // ---- V rows: direct [c][n] stores ----
        #pragma unroll
        for (int i = 0; i < 2; i++) {
            #pragma unroll
            for (int h = 0; h < 2; h++) {
                int col = wc + 16*i + g + 8*h;          // local co
                int c = co0 - 128 + col;                // V channel
                float bias = g_ball[co0 + col];
                __half* dst = g_V + ((size_t)b*CC + c)*NPIX + n0;
                #pragma unroll
                for (int j = 0; j < 8; j++) {
                    int n = wn + 8*j + t4*2;
                    *(uint32_t*)(dst + n) =
                        packh(acc[i][j][2*h] + bias, acc[i][j][2*h+1] + bias);
                }
            }
        }
    } else {
        // ---- Q/K rows: transpose through smem (reuse W region) ----
        __syncthreads();
        #pragma unroll
        for (int i = 0; i < 2; i++)
            #pragma unroll
            for (int h = 0; h < 2; h++) {
                int col = wc + 16*i + g + 8*h;
                float bias = g_ball[col];
                #pragma unroll
                for (int j = 0; j < 8; j++) {
                    int n = wn + 8*j + t4*2;
                    psm[PW_O + n*LDT + col]     = __float2half(acc[i][j][2*h]   + bias);
                    psm[PW_O + (n+1)*LDT + col] = __float2half(acc[i][j][2*h+1] + bias);
                }
            }
        __syncthreads();
        // rows n: cols 0..63 -> Q[n][cq], 64..127 -> K[n][cq]
        #pragma unroll
        for (int r = 0; r < 8; r++) {
            int id = tid + 256*r, nl = id >> 4, ch = id & 15;
            uint4 v = *(uint4*)&psm[PW_O + nl*LDT + ch*8];
            size_t nglob = (size_t)b*NPIX + n0 + nl;
            if (ch < 8) *(uint4*)(g_Q + nglob*CQ + ch*8) = v;
            else        *(uint4*)(g_K + nglob*CQ + (ch-8)*8) = v;
        }
    }
}

// ================= Kernel 2: fused attention, fp16 (unchanged from R11) ====
#define SM_K  0
#define SM_S  4608
#define Q_ST(s) (9216 + (s)*4608)
#define V_ST(s) (18432 + (s)*18432)
#define SMEM_HALVES (18432 + 2*18432)
#define SMEM_BYTES  (SMEM_HALVES*2)

__global__ void __launch_bounds__(256) attn_mma(float* __restrict__ out,
                                                const float* __restrict__ gbias) {
    extern __shared__ __half sm[];
    const uint32_t sb = smem_u32(sm);
    const int tid = threadIdx.x, wid = tid >> 5, lane = tid & 31;
    const int g = lane >> 2, t4 = lane & 3;
    const int b = blockIdx.y, m0 = blockIdx.x * 64;
    const int lrow = lane & 15, lcol = (lane >> 4) * 8;

    const int w1m = (wid & 1) * 32, w1n = (wid >> 1) * 16;   // GEMM1 [32m x 16n]
    const int w2c = (wid >> 1) * 64, w2m = (wid & 1) * 32;   // GEMM2 [64c x 32m]

    #define SMB(idx) (sb + (uint32_t)(idx) * 2u)

    auto issue_stage = [&](int s, int n0s) {
        const __half* q = g_Q + ((size_t)b*NPIX + n0s)*CQ;
        #pragma unroll
        for (int r = 0; r < 2; r++) {
            int id = tid + 256*r, row = id >> 3, ch = (id & 7) * 8;
            cpa16(SMB(Q_ST(s) + row*LD + ch), q + (size_t)row*CQ + ch);
        }
        const __half* v = g_V + (size_t)b*CC*NPIX + n0s;
        #pragma unroll
        for (int r = 0; r < 8; r++) {
            int id = tid + 256*r, row = id >> 3, ch = (id & 7) * 8;
            cpa16(SMB(V_ST(s) + row*LD + ch), v + (size_t)row*NPIX + ch);
        }
    };

    {   // K prologue (group 0, with stage 0)
        const __half* k = g_K + ((size_t)b*NPIX + m0)*CQ;
        #pragma unroll
        for (int r = 0; r < 2; r++) {
            int id = tid + 256*r, row = id >> 3, ch = (id & 7) * 8;
            cpa16(SMB(SM_K + row*LD + ch), k + (size_t)row*CQ + ch);
        }
    }
    issue_stage(0, 0);
    CP_COMMIT();

    float acc[4][4][4];
    #pragma unroll
    for (int i = 0; i < 4; i++)
        #pragma unroll
        for (int j = 0; j < 4; j++)
            #pragma unroll
            for (int q = 0; q < 4; q++) acc[i][j][q] = 0.f;

    for (int it = 0; it < 64; ++it) {
        const int buf = it & 1;
        CP_WAIT0();
        __syncthreads();
        if (it < 63) { issue_stage(buf ^ 1, (it + 1) * 64); CP_COMMIT(); }

        const uint32_t QO = Q_ST(buf), VO = V_ST(buf);

        // ---- GEMM1: S[m][n] = K·Q ----
        float sacc[2][2][4];
        #pragma unroll
        for (int i = 0; i < 2; i++)
            #pragma unroll
            for (int j = 0; j < 2; j++)
                #pragma unroll
                for (int q = 0; q < 4; q++) sacc[i][j][q] = 0.f;

        #pragma unroll
        for (int kk = 0; kk < 4; kk++) {
            const int C = kk * 16 + lcol;
            uint32_t k0[4], k1[4], qv[4];
            ldsm4(k0, SMB(SM_K + (w1m      + lrow)*LD + C));
            ldsm4(k1, SMB(SM_K + (w1m + 16 + lrow)*LD + C));
            ldsm4(qv, SMB(QO   + (w1n      + lrow)*LD + C));
            mmah(sacc[0][0], k0, qv[0], qv[2]);
            mmah(sacc[0][1], k0, qv[1], qv[3]);
            mmah(sacc[1][0], k1, qv[0], qv[2]);
            mmah(sacc[1][1], k1, qv[1], qv[3]);
        }

        // ---- elu + store S (fp16), layout [m][n] ----
        #pragma unroll
        for (int i = 0; i < 2; i++)
            #pragma unroll
            for (int j = 0; j < 2; j++) {
                int row = w1m + 16*i + g;
                int col = w1n + 8*j + t4*2;
                *(uint32_t*)&sm[SM_S + row*LD + col] =
                    packh(elu_raw(sacc[i][j][0]), elu_raw(sacc[i][j][1]));
                *(uint32_t*)&sm[SM_S + (row+8)*LD + col] =
                    packh(elu_raw(sacc[i][j][2]), elu_raw(sacc[i][j][3]));
            }
        __syncthreads();

        // ---- GEMM2: O[c][m] += V·S ----
        #pragma unroll
        for (int kk = 0; kk < 4; kk++) {
            const int C = kk * 16 + lcol;
            uint32_t vv[4][4], s0[4], s1[4];
            #pragma unroll
            for (int i = 0; i < 4; i++)
                ldsm4(vv[i], SMB(VO + (w2c + 16*i + lrow)*LD + C));
            ldsm4(s0, SMB(SM_S + (w2m      + lrow)*LD + C));
            ldsm4(s1, SMB(SM_S + (w2m + 16 + lrow)*LD + C));
            #pragma unroll
            for (int i = 0; i < 4; i++) {
                mmah(acc[i][0], vv[i], s0[0], s0[2]);
                mmah(acc[i][1], vv[i], s0[1], s0[3]);
                mmah(acc[i][2], vv[i], s1[0], s1[2]);
                mmah(acc[i][3], vv[i], s1[1], s1[3]);
            }
        }
    }

    // ---- epilogue: out = acc/4096 + gbias[c] ----
    const float inv = 1.0f / 4096.0f;
    #pragma unroll
    for (int i = 0; i < 4; i++) {
        int c  = w2c + 16*i + g;
        float b0 = gbias[c], b8 = gbias[c + 8];
        #pragma unroll
        for (int j = 0; j < 4; j++) {
            int m = m0 + w2m + 8*j + t4*2;
            float2 v0 = { fmaf(acc[i][j][0], inv, b0), fmaf(acc[i][j][1], inv, b0) };
            *(float2*)&out[((size_t)b*CC + c)*NPIX + m] = v0;
            float2 v1 = { fmaf(acc[i][j][2], inv, b8), fmaf(acc[i][j][3], inv, b8) };
            *(float2*)&out[((size_t)b*CC + c + 8)*NPIX + m] = v1;
        }
    }
}

// ================= launch =================
extern "C" void kernel_launch(void* const* d_in, const int* in_sizes, int n_in,
                              void* d_out, int out_size) {
    const float* x  = (const float*)d_in[0];
    const float* qw = (const float*)d_in[1];
    const float* qb = (const float*)d_in[2];
    const float* kw = (const float*)d_in[3];
    const float* kb = (const float*)d_in[4];
    const float* vw = (const float*)d_in[5];
    const float* vb = (const float*)d_in[6];
    const float* gw = (const float*)d_in[7];
    const float* gb = (const float*)d_in[8];
    float* out = (float*)d_out;

    cudaFuncSetAttribute(attn_mma, cudaFuncAttributeMaxDynamicSharedMemorySize, SMEM_BYTES);
    cudaFuncSetAttribute(proj_mma, cudaFuncAttributeMaxDynamicSharedMemorySize, PROJ_SMEM);

    build_weights<<<ROWS_ALL, 256>>>(qw, qb, kw, kb, vw, vb, gw);
    cvt_x<<<2048, 256>>>(x);
    proj_mma<<<dim3(32, 3, BB), 256, PROJ_SMEM>>>(nullptr);
    attn_mma<<<dim3(64, BB), 256, SMEM_BYTES>>>(out, gb);
}